// round 2
// baseline (speedup 1.0000x reference)
#include <cuda_runtime.h>

#define S_TOT 3137
#define NPIX  3136
#define NHEAD 8
#define HD    32
#define CDIM  256
#define BATCH 4
#define BQ    64
#define BK    64
#define ATT_SCALE 0.17677669529663687f  // 32^-0.5

// scratch (allocation-free rule: device globals)
__device__ float g_Q[BATCH*NHEAD*S_TOT*HD];
__device__ float g_K[BATCH*NHEAD*S_TOT*HD];
__device__ float g_V[BATCH*NHEAD*S_TOT*HD];
__device__ float g_AO[BATCH*S_TOT*CDIM];

// ---------------------------------------------------------------------------
// QKV GEMM: [B*S_TOT, 256] @ qkv_w^T(768,256) -> scatter into g_Q/g_K/g_V
// ---------------------------------------------------------------------------
__global__ void qkv_gemm(const float* __restrict__ x,
                         const float* __restrict__ cls,
                         const float* __restrict__ w) {
    __shared__ float Xt[32][68];
    __shared__ float Wt[32][68];
    const int tid = threadIdx.x;
    const int ty = tid >> 3, tx = tid & 7;
    const int m0 = blockIdx.x * 64, n0 = blockIdx.y * 64;
    const int M = BATCH * S_TOT;

    float acc[4][8];
#pragma unroll
    for (int i = 0; i < 4; i++)
#pragma unroll
        for (int j = 0; j < 8; j++) acc[i][j] = 0.f;

    for (int kc = 0; kc < 256; kc += 32) {
#pragma unroll
        for (int t = 0; t < 4; t++) {
            int g = tid + t * 128;
            int r = g >> 3, c4 = g & 7;
            int m = m0 + r;
            float4 v = make_float4(0.f, 0.f, 0.f, 0.f);
            if (m < M) {
                int b = m / S_TOT, s = m % S_TOT;
                const float* src = (s == 0) ? (cls + b * CDIM)
                                            : (x + (size_t)(b * NPIX + (s - 1)) * CDIM);
                v = *(const float4*)(src + kc + c4 * 4);
            }
            Xt[c4 * 4 + 0][r] = v.x; Xt[c4 * 4 + 1][r] = v.y;
            Xt[c4 * 4 + 2][r] = v.z; Xt[c4 * 4 + 3][r] = v.w;

            int n = n0 + r;
            float4 wv = *(const float4*)(w + (size_t)n * 256 + kc + c4 * 4);
            Wt[c4 * 4 + 0][r] = wv.x; Wt[c4 * 4 + 1][r] = wv.y;
            Wt[c4 * 4 + 2][r] = wv.z; Wt[c4 * 4 + 3][r] = wv.w;
        }
        __syncthreads();
#pragma unroll
        for (int kk = 0; kk < 32; kk++) {
            float4 xv  = *(float4*)&Xt[kk][ty * 4];
            float4 wv0 = *(float4*)&Wt[kk][tx * 8];
            float4 wv1 = *(float4*)&Wt[kk][tx * 8 + 4];
            float xr[4] = {xv.x, xv.y, xv.z, xv.w};
            float wr[8] = {wv0.x, wv0.y, wv0.z, wv0.w, wv1.x, wv1.y, wv1.z, wv1.w};
#pragma unroll
            for (int i = 0; i < 4; i++)
#pragma unroll
                for (int j = 0; j < 8; j++) acc[i][j] += xr[i] * wr[j];
        }
        __syncthreads();
    }

#pragma unroll
    for (int i = 0; i < 4; i++) {
        int m = m0 + ty * 4 + i;
        if (m >= M) continue;
        int b = m / S_TOT, s = m % S_TOT;
#pragma unroll
        for (int jj = 0; jj < 2; jj++) {
            int n = n0 + tx * 8 + jj * 4;
            int sec = n >> 8, h = (n >> 5) & 7, d = n & 31;
            float* base = (sec == 0) ? g_Q : ((sec == 1) ? g_K : g_V);
            float4 v = make_float4(acc[i][jj * 4], acc[i][jj * 4 + 1],
                                   acc[i][jj * 4 + 2], acc[i][jj * 4 + 3]);
            *(float4*)&base[(((size_t)(b * NHEAD + h) * S_TOT + s) * HD) + d] = v;
        }
    }
}

// ---------------------------------------------------------------------------
// Flash attention, fp32. Grid: (ceil(S/64), B*NHEAD). Block: 128 threads.
// ---------------------------------------------------------------------------
__global__ void attn_kernel() {
    __shared__ float Qt[32][68];
    __shared__ float Kt[32][68];
    __shared__ float Vs[64][36];
    __shared__ float Ps[64][68];
    __shared__ float m_s[64], l_s[64], a_s[64];

    const int tid = threadIdx.x;
    const int ty = tid >> 3, tx = tid & 7;
    const int q0 = blockIdx.x * BQ;
    const int bh = blockIdx.y;
    const float* Qg = g_Q + (size_t)bh * S_TOT * HD;
    const float* Kg = g_K + (size_t)bh * S_TOT * HD;
    const float* Vg = g_V + (size_t)bh * S_TOT * HD;

    // load Q tile transposed
#pragma unroll
    for (int t = 0; t < 4; t++) {
        int g = tid + t * 128;
        int r = g >> 3, c4 = g & 7;
        float4 v = make_float4(0.f, 0.f, 0.f, 0.f);
        if (q0 + r < S_TOT) v = *(const float4*)(Qg + (size_t)(q0 + r) * HD + c4 * 4);
        Qt[c4 * 4 + 0][r] = v.x; Qt[c4 * 4 + 1][r] = v.y;
        Qt[c4 * 4 + 2][r] = v.z; Qt[c4 * 4 + 3][r] = v.w;
    }
    if (tid < 64) { m_s[tid] = -1e30f; l_s[tid] = 0.f; }

    float o[4][4];
#pragma unroll
    for (int i = 0; i < 4; i++)
#pragma unroll
        for (int j = 0; j < 4; j++) o[i][j] = 0.f;

    const int ntiles = (S_TOT + BK - 1) / BK;
    for (int kt = 0; kt < ntiles; kt++) {
        __syncthreads();  // protect Kt/Vs/Ps from previous-iter readers
        const int k0 = kt * BK;
#pragma unroll
        for (int t = 0; t < 4; t++) {
            int g = tid + t * 128;
            int r = g >> 3, c4 = g & 7;
            float4 kv = make_float4(0.f, 0.f, 0.f, 0.f);
            float4 vv = make_float4(0.f, 0.f, 0.f, 0.f);
            if (k0 + r < S_TOT) {
                kv = *(const float4*)(Kg + (size_t)(k0 + r) * HD + c4 * 4);
                vv = *(const float4*)(Vg + (size_t)(k0 + r) * HD + c4 * 4);
            }
            Kt[c4 * 4 + 0][r] = kv.x; Kt[c4 * 4 + 1][r] = kv.y;
            Kt[c4 * 4 + 2][r] = kv.z; Kt[c4 * 4 + 3][r] = kv.w;
            *(float4*)&Vs[r][c4 * 4] = vv;
        }
        __syncthreads();

        // S = Q K^T tile (64x64), mapping A: rows ty*4+i, cols tx*8+j
        float s[4][8];
#pragma unroll
        for (int i = 0; i < 4; i++)
#pragma unroll
            for (int j = 0; j < 8; j++) s[i][j] = 0.f;
#pragma unroll
        for (int kk = 0; kk < 32; kk++) {
            float4 qv  = *(float4*)&Qt[kk][ty * 4];
            float4 kv0 = *(float4*)&Kt[kk][tx * 8];
            float4 kv1 = *(float4*)&Kt[kk][tx * 8 + 4];
            float qr[4] = {qv.x, qv.y, qv.z, qv.w};
            float kr[8] = {kv0.x, kv0.y, kv0.z, kv0.w, kv1.x, kv1.y, kv1.z, kv1.w};
#pragma unroll
            for (int i = 0; i < 4; i++)
#pragma unroll
                for (int j = 0; j < 8; j++) s[i][j] += qr[i] * kr[j];
        }

        // online softmax per row (reduce over 8 lanes sharing ty)
#pragma unroll
        for (int i = 0; i < 4; i++) {
            int row = ty * 4 + i;
            float rm = -1e30f;
#pragma unroll
            for (int j = 0; j < 8; j++) {
                int kg = k0 + tx * 8 + j;
                s[i][j] = (kg < S_TOT) ? s[i][j] * ATT_SCALE : -1e30f;
                rm = fmaxf(rm, s[i][j]);
            }
            rm = fmaxf(rm, __shfl_xor_sync(0xffffffffu, rm, 1));
            rm = fmaxf(rm, __shfl_xor_sync(0xffffffffu, rm, 2));
            rm = fmaxf(rm, __shfl_xor_sync(0xffffffffu, rm, 4));
            float mold = m_s[row];
            float mnew = fmaxf(mold, rm);
            float rs = 0.f;
#pragma unroll
            for (int j = 0; j < 8; j++) {
                float p = __expf(s[i][j] - mnew);
                s[i][j] = p;
                rs += p;
            }
            rs += __shfl_xor_sync(0xffffffffu, rs, 1);
            rs += __shfl_xor_sync(0xffffffffu, rs, 2);
            rs += __shfl_xor_sync(0xffffffffu, rs, 4);
            if (tx == 0) {
                float al = __expf(mold - mnew);
                m_s[row] = mnew;
                l_s[row] = l_s[row] * al + rs;
                a_s[row] = al;
            }
            *(float4*)&Ps[row][tx * 8]     = make_float4(s[i][0], s[i][1], s[i][2], s[i][3]);
            *(float4*)&Ps[row][tx * 8 + 4] = make_float4(s[i][4], s[i][5], s[i][6], s[i][7]);
        }
        __syncthreads();

        // O += P V, mapping B: rows ty*4+i, cols tx*4+j
        float al[4];
#pragma unroll
        for (int i = 0; i < 4; i++) {
            al[i] = a_s[ty * 4 + i];
#pragma unroll
            for (int j = 0; j < 4; j++) o[i][j] *= al[i];
        }
#pragma unroll 8
        for (int kk = 0; kk < 64; kk++) {
            float4 vv = *(float4*)&Vs[kk][tx * 4];
            float vr[4] = {vv.x, vv.y, vv.z, vv.w};
            float pv[4];
#pragma unroll
            for (int i = 0; i < 4; i++) pv[i] = Ps[ty * 4 + i][kk];
#pragma unroll
            for (int i = 0; i < 4; i++)
#pragma unroll
                for (int j = 0; j < 4; j++) o[i][j] += pv[i] * vr[j];
        }
    }

    // epilogue: normalize and write [B, S, C] with c = h*32+d
    const int b = bh >> 3, h = bh & 7;
#pragma unroll
    for (int i = 0; i < 4; i++) {
        int row = ty * 4 + i;
        int qg = q0 + row;
        if (qg < S_TOT) {
            float inv = 1.f / l_s[row];
            float4 v = make_float4(o[i][0] * inv, o[i][1] * inv,
                                   o[i][2] * inv, o[i][3] * inv);
            *(float4*)&g_AO[((size_t)(b * S_TOT + qg)) * CDIM + h * HD + tx * 4] = v;
        }
    }
}

// ---------------------------------------------------------------------------
// LePE depthwise 5x5 conv, adds into g_AO spatial rows. Block: 256 thr, 16 pos.
// ---------------------------------------------------------------------------
__global__ void lepe_kernel(const float* __restrict__ x,
                            const float* __restrict__ lw,
                            const float* __restrict__ lb) {
    const int c = threadIdx.x;
    const int p0 = blockIdx.x * 16;
    float w[25];
#pragma unroll
    for (int j = 0; j < 25; j++) w[j] = lw[c * 25 + j];
    const float bias = lb[c];
#pragma unroll 1
    for (int p = 0; p < 16; p++) {
        int pos = p0 + p;
        int b = pos / NPIX;
        int n = pos % NPIX;
        int y = n / 56, xx = n % 56;
        float acc = bias;
#pragma unroll
        for (int ky = -2; ky <= 2; ky++) {
            int yy = y + ky;
            if (yy < 0 || yy >= 56) continue;
#pragma unroll
            for (int kx = -2; kx <= 2; kx++) {
                int xc = xx + kx;
                if (xc < 0 || xc >= 56) continue;
                acc += x[((size_t)((b * 56 + yy) * 56 + xc)) * CDIM + c] *
                       w[(ky + 2) * 5 + (kx + 2)];
            }
        }
        g_AO[((size_t)(b * S_TOT + 1 + n)) * CDIM + c] += acc;
    }
}

// ---------------------------------------------------------------------------
// Projection GEMM with bias, routes rows to x_out / cls_out regions of d_out
// ---------------------------------------------------------------------------
__global__ void proj_gemm(const float* __restrict__ w,
                          const float* __restrict__ bias,
                          float* __restrict__ out) {
    __shared__ float Xt[32][68];
    __shared__ float Wt[32][68];
    const int tid = threadIdx.x;
    const int ty = tid >> 3, tx = tid & 7;
    const int m0 = blockIdx.x * 64, n0 = blockIdx.y * 64;
    const int M = BATCH * S_TOT;

    float acc[4][8];
#pragma unroll
    for (int i = 0; i < 4; i++)
#pragma unroll
        for (int j = 0; j < 8; j++) acc[i][j] = 0.f;

    for (int kc = 0; kc < 256; kc += 32) {
#pragma unroll
        for (int t = 0; t < 4; t++) {
            int g = tid + t * 128;
            int r = g >> 3, c4 = g & 7;
            int m = m0 + r;
            float4 v = make_float4(0.f, 0.f, 0.f, 0.f);
            if (m < M) v = *(const float4*)(g_AO + (size_t)m * CDIM + kc + c4 * 4);
            Xt[c4 * 4 + 0][r] = v.x; Xt[c4 * 4 + 1][r] = v.y;
            Xt[c4 * 4 + 2][r] = v.z; Xt[c4 * 4 + 3][r] = v.w;

            int n = n0 + r;
            float4 wv = *(const float4*)(w + (size_t)n * 256 + kc + c4 * 4);
            Wt[c4 * 4 + 0][r] = wv.x; Wt[c4 * 4 + 1][r] = wv.y;
            Wt[c4 * 4 + 2][r] = wv.z; Wt[c4 * 4 + 3][r] = wv.w;
        }
        __syncthreads();
#pragma unroll
        for (int kk = 0; kk < 32; kk++) {
            float4 xv  = *(float4*)&Xt[kk][ty * 4];
            float4 wv0 = *(float4*)&Wt[kk][tx * 8];
            float4 wv1 = *(float4*)&Wt[kk][tx * 8 + 4];
            float xr[4] = {xv.x, xv.y, xv.z, xv.w};
            float wr[8] = {wv0.x, wv0.y, wv0.z, wv0.w, wv1.x, wv1.y, wv1.z, wv1.w};
#pragma unroll
            for (int i = 0; i < 4; i++)
#pragma unroll
                for (int j = 0; j < 8; j++) acc[i][j] += xr[i] * wr[j];
        }
        __syncthreads();
    }

    const size_t cls_base = (size_t)BATCH * NPIX * CDIM;
#pragma unroll
    for (int i = 0; i < 4; i++) {
        int m = m0 + ty * 4 + i;
        if (m >= M) continue;
        int b = m / S_TOT, s = m % S_TOT;
#pragma unroll
        for (int jj = 0; jj < 2; jj++) {
            int n = n0 + tx * 8 + jj * 4;
            float4 bb = *(const float4*)(bias + n);
            float4 v = make_float4(acc[i][jj * 4] + bb.x, acc[i][jj * 4 + 1] + bb.y,
                                   acc[i][jj * 4 + 2] + bb.z, acc[i][jj * 4 + 3] + bb.w);
            float* dst;
            if (s == 0) dst = out + cls_base + (size_t)b * CDIM + n;
            else        dst = out + ((size_t)(b * NPIX + (s - 1))) * CDIM + n;
            *(float4*)dst = v;
        }
    }
}

// ---------------------------------------------------------------------------
extern "C" void kernel_launch(void* const* d_in, const int* in_sizes, int n_in,
                              void* d_out, int out_size) {
    (void)in_sizes; (void)n_in; (void)out_size;
    const float* x      = (const float*)d_in[0];
    const float* cls    = (const float*)d_in[1];
    const float* qkv_w  = (const float*)d_in[2];
    const float* proj_w = (const float*)d_in[3];
    const float* proj_b = (const float*)d_in[4];
    const float* lepe_w = (const float*)d_in[5];
    const float* lepe_b = (const float*)d_in[6];
    float* out = (float*)d_out;

    const int M = BATCH * S_TOT;                 // 12548
    dim3 qkvGrid((M + 63) / 64, 768 / 64);       // 197 x 12
    qkv_gemm<<<qkvGrid, 128>>>(x, cls, qkv_w);

    dim3 attGrid((S_TOT + BQ - 1) / BQ, BATCH * NHEAD);  // 50 x 32
    attn_kernel<<<attGrid, 128>>>();

    lepe_kernel<<<(BATCH * NPIX) / 16, 256>>>(x, lepe_w, lepe_b);

    dim3 projGrid((M + 63) / 64, 256 / 64);      // 197 x 4
    proj_gemm<<<projGrid, 128>>>(proj_w, proj_b, out);
}

// round 10
// speedup vs baseline: 2.1503x; 2.1503x over previous
#include <cuda_runtime.h>
#include <cstdint>

#define S_TOT 3137
#define NPIX  3136
#define NHEAD 8
#define HD    32
#define CDIM  256
#define BATCH 4
#define ATT_SCALE 0.17677669529663687f  // 32^-0.5

// ---------------------------------------------------------------------------
// scratch (allocation-free rule: device globals)
// ---------------------------------------------------------------------------
__device__ float g_Q[BATCH*NHEAD*S_TOT*HD];
__device__ float g_K[BATCH*NHEAD*S_TOT*HD];
__device__ float g_V[BATCH*NHEAD*S_TOT*HD];
__device__ float g_AO[BATCH*S_TOT*CDIM];

// ---------------------------------------------------------------------------
// mma.sync tf32 helpers (baseline sm_80 PTX — valid on compute_103)
// ---------------------------------------------------------------------------
__device__ __forceinline__ uint32_t f2tf(float f) {
    uint32_t u;
    asm("cvt.rna.tf32.f32 %0, %1;" : "=r"(u) : "f"(f));
    return u;
}
__device__ __forceinline__ void mma_tf32(float c[4],
                                         uint32_t a0, uint32_t a1, uint32_t a2, uint32_t a3,
                                         uint32_t b0, uint32_t b1) {
    asm volatile("mma.sync.aligned.m16n8k8.row.col.f32.tf32.tf32.f32 "
                 "{%0,%1,%2,%3}, {%4,%5,%6,%7}, {%8,%9}, {%0,%1,%2,%3};"
                 : "+f"(c[0]), "+f"(c[1]), "+f"(c[2]), "+f"(c[3])
                 : "r"(a0), "r"(a1), "r"(a2), "r"(a3), "r"(b0), "r"(b1));
}

// ---------------------------------------------------------------------------
// QKV GEMM: [B*S,256] @ qkv_w^T -> g_Q/g_K/g_V [bh][s][hd]
// ---------------------------------------------------------------------------
__global__ void qkv_gemm(const float* __restrict__ x,
                         const float* __restrict__ cls,
                         const float* __restrict__ w) {
    __shared__ float Xt[32][68];
    __shared__ float Wt[32][68];
    const int tid = threadIdx.x;
    const int ty = tid >> 3, tx = tid & 7;
    const int m0 = blockIdx.x * 64, n0 = blockIdx.y * 64;
    const int M = BATCH * S_TOT;

    float acc[4][8];
#pragma unroll
    for (int i = 0; i < 4; i++)
#pragma unroll
        for (int j = 0; j < 8; j++) acc[i][j] = 0.f;

    for (int kc = 0; kc < 256; kc += 32) {
#pragma unroll
        for (int t = 0; t < 4; t++) {
            int g = tid + t * 128;
            int r = g >> 3, c4 = g & 7;
            int m = m0 + r;
            float4 v = make_float4(0.f, 0.f, 0.f, 0.f);
            if (m < M) {
                int b = m / S_TOT, s = m % S_TOT;
                const float* src = (s == 0) ? (cls + b * CDIM)
                                            : (x + (size_t)(b * NPIX + (s - 1)) * CDIM);
                v = *(const float4*)(src + kc + c4 * 4);
            }
            Xt[c4 * 4 + 0][r] = v.x; Xt[c4 * 4 + 1][r] = v.y;
            Xt[c4 * 4 + 2][r] = v.z; Xt[c4 * 4 + 3][r] = v.w;
            int n = n0 + r;
            float4 wv = *(const float4*)(w + (size_t)n * 256 + kc + c4 * 4);
            Wt[c4 * 4 + 0][r] = wv.x; Wt[c4 * 4 + 1][r] = wv.y;
            Wt[c4 * 4 + 2][r] = wv.z; Wt[c4 * 4 + 3][r] = wv.w;
        }
        __syncthreads();
#pragma unroll
        for (int kk = 0; kk < 32; kk++) {
            float4 xv  = *(float4*)&Xt[kk][ty * 4];
            float4 wv0 = *(float4*)&Wt[kk][tx * 8];
            float4 wv1 = *(float4*)&Wt[kk][tx * 8 + 4];
            float xr[4] = {xv.x, xv.y, xv.z, xv.w};
            float wr[8] = {wv0.x, wv0.y, wv0.z, wv0.w, wv1.x, wv1.y, wv1.z, wv1.w};
#pragma unroll
            for (int i = 0; i < 4; i++)
#pragma unroll
                for (int j = 0; j < 8; j++) acc[i][j] += xr[i] * wr[j];
        }
        __syncthreads();
    }

#pragma unroll
    for (int i = 0; i < 4; i++) {
        int m = m0 + ty * 4 + i;
        if (m >= M) continue;
        int b = m / S_TOT, s = m % S_TOT;
#pragma unroll
        for (int jj = 0; jj < 2; jj++) {
            int n = n0 + tx * 8 + jj * 4;
            int sec = n >> 8, h = (n >> 5) & 7, d = n & 31;
            float* base = (sec == 0) ? g_Q : ((sec == 1) ? g_K : g_V);
            float4 v = make_float4(acc[i][jj * 4], acc[i][jj * 4 + 1],
                                   acc[i][jj * 4 + 2], acc[i][jj * 4 + 3]);
            *(float4*)&base[(((size_t)(b * NHEAD + h) * S_TOT + s) * HD) + d] = v;
        }
    }
}

// ---------------------------------------------------------------------------
// Flash attention via mma.sync tf32 (no-max softmax; logits are tiny here).
// 256 threads = 8 warps; warp w owns query rows [q0+16w, q0+16w+16).
// Key tiles of 64; O accumulates in registers across all 50 tiles.
// P re-fragmented from the S C-fragment via warp shuffles (no SMEM roundtrip).
// Static SMEM: Qs 18KB + Ks 9KB + Vs 10KB = 37KB (no opt-in needed).
// ---------------------------------------------------------------------------
#define NKT_64 50

__global__ void __launch_bounds__(256) attn_mma() {
    __shared__ uint32_t Qs[128 * 36];
    __shared__ uint32_t Ks[64 * 36];
    __shared__ uint32_t Vs[64 * 40];

    const int tid  = threadIdx.x;
    const int lane = tid & 31;
    const int warp = tid >> 5;
    const int g  = lane >> 2;   // row within m-tile
    const int t4 = lane & 3;    // thread in quad
    const int L0 = (lane & ~3) + (t4 >> 1);  // shfl src for P cols t4
    const int L1 = L0 + 2;                   // shfl src for P cols t4+4
    const bool odd = t4 & 1;
    const int q0 = blockIdx.x * 128;
    const int bh = blockIdx.y;

    const float* Qg = g_Q + (size_t)bh * S_TOT * HD;
    const float* Kg = g_K + (size_t)bh * S_TOT * HD;
    const float* Vg = g_V + (size_t)bh * S_TOT * HD;

    // ---- load Q tile (tf32-converted) ----
    {
        int row = tid >> 1, half = tid & 1;
        int qg = q0 + row;
        bool ok = qg < S_TOT;
        const float* src = Qg + (size_t)(ok ? qg : 0) * HD + half * 16;
        uint32_t* dst = Qs + row * 36 + half * 16;
#pragma unroll
        for (int i = 0; i < 4; i++) {
            float4 v = ok ? *(const float4*)(src + i * 4) : make_float4(0.f,0.f,0.f,0.f);
            dst[i * 4 + 0] = f2tf(v.x);
            dst[i * 4 + 1] = f2tf(v.y);
            dst[i * 4 + 2] = f2tf(v.z);
            dst[i * 4 + 3] = f2tf(v.w);
        }
    }
    __syncthreads();

    // ---- preload Q A-fragments (reused every key tile) ----
    const int wr = warp * 16;
    uint32_t qa[4][4];
#pragma unroll
    for (int ks = 0; ks < 4; ks++) {
        int c = ks * 8 + t4;
        qa[ks][0] = Qs[(wr + g) * 36 + c];
        qa[ks][1] = Qs[(wr + g + 8) * 36 + c];
        qa[ks][2] = Qs[(wr + g) * 36 + c + 4];
        qa[ks][3] = Qs[(wr + g + 8) * 36 + c + 4];
    }

    float o[4][4];
#pragma unroll
    for (int nt = 0; nt < 4; nt++)
#pragma unroll
        for (int c = 0; c < 4; c++) o[nt][c] = 0.f;
    float l0 = 0.f, l1 = 0.f;

    for (int kt = 0; kt < NKT_64; kt++) {
        __syncthreads();  // protect Ks/Vs from previous-iter readers

        // ---- load K/V tile (tf32-converted) ----
        {
            int row = tid >> 2, q4 = tid & 3;
            int kr = kt * 64 + row;
            bool ok = kr < S_TOT;
            const float* ks_ = Kg + (size_t)(ok ? kr : 0) * HD + q4 * 8;
            const float* vs_ = Vg + (size_t)(ok ? kr : 0) * HD + q4 * 8;
            uint32_t* kd = Ks + row * 36 + q4 * 8;
            uint32_t* vd = Vs + row * 40 + q4 * 8;
#pragma unroll
            for (int i = 0; i < 2; i++) {
                float4 kv = ok ? *(const float4*)(ks_ + i * 4) : make_float4(0.f,0.f,0.f,0.f);
                float4 vv = ok ? *(const float4*)(vs_ + i * 4) : make_float4(0.f,0.f,0.f,0.f);
                kd[i * 4 + 0] = f2tf(kv.x); kd[i * 4 + 1] = f2tf(kv.y);
                kd[i * 4 + 2] = f2tf(kv.z); kd[i * 4 + 3] = f2tf(kv.w);
                vd[i * 4 + 0] = f2tf(vv.x); vd[i * 4 + 1] = f2tf(vv.y);
                vd[i * 4 + 2] = f2tf(vv.z); vd[i * 4 + 3] = f2tf(vv.w);
            }
        }
        __syncthreads();

        // ---- MMA1: S(16x64) = Q(16x32) @ K^T ----
        float s[8][4];
#pragma unroll
        for (int nt = 0; nt < 8; nt++)
#pragma unroll
            for (int c = 0; c < 4; c++) s[nt][c] = 0.f;
#pragma unroll
        for (int ks = 0; ks < 4; ks++) {
#pragma unroll
            for (int nt = 0; nt < 8; nt++) {
                uint32_t b0 = Ks[(nt * 8 + g) * 36 + ks * 8 + t4];
                uint32_t b1 = Ks[(nt * 8 + g) * 36 + ks * 8 + t4 + 4];
                mma_tf32(s[nt], qa[ks][0], qa[ks][1], qa[ks][2], qa[ks][3], b0, b1);
            }
        }

        // ---- softmax (no max-sub), masked for OOB keys; in-register ----
        float l0a = 0.f, l1a = 0.f;
#pragma unroll
        for (int nt = 0; nt < 8; nt++) {
            int kb = kt * 64 + nt * 8 + 2 * t4;
            float p0 = (kb     < S_TOT) ? __expf(s[nt][0] * ATT_SCALE) : 0.f;
            float p1 = (kb + 1 < S_TOT) ? __expf(s[nt][1] * ATT_SCALE) : 0.f;
            float p2 = (kb     < S_TOT) ? __expf(s[nt][2] * ATT_SCALE) : 0.f;
            float p3 = (kb + 1 < S_TOT) ? __expf(s[nt][3] * ATT_SCALE) : 0.f;
            l0a += p0 + p1;
            l1a += p2 + p3;
            s[nt][0] = p0; s[nt][1] = p1; s[nt][2] = p2; s[nt][3] = p3;
        }
        l0a += __shfl_xor_sync(0xffffffffu, l0a, 1);
        l0a += __shfl_xor_sync(0xffffffffu, l0a, 2);
        l1a += __shfl_xor_sync(0xffffffffu, l1a, 1);
        l1a += __shfl_xor_sync(0xffffffffu, l1a, 2);
        l0 += l0a; l1 += l1a;

        // ---- MMA2: O(16x32) += P(16x64) @ V(64x32) ----
        // A-fragment of P via shfl: P[g][c] lives in lane (g*4 + c/2), slot c&1
        // (slots 2/3 for row g+8).
#pragma unroll
        for (int ks = 0; ks < 8; ks++) {
            float e0 = __shfl_sync(0xffffffffu, s[ks][0], L0);
            float e1 = __shfl_sync(0xffffffffu, s[ks][1], L0);
            float e2 = __shfl_sync(0xffffffffu, s[ks][2], L0);
            float e3 = __shfl_sync(0xffffffffu, s[ks][3], L0);
            float f0 = __shfl_sync(0xffffffffu, s[ks][0], L1);
            float f1 = __shfl_sync(0xffffffffu, s[ks][1], L1);
            float f2 = __shfl_sync(0xffffffffu, s[ks][2], L1);
            float f3 = __shfl_sync(0xffffffffu, s[ks][3], L1);
            uint32_t a0 = f2tf(odd ? e1 : e0);   // P[g][ks*8+t4]
            uint32_t a1 = f2tf(odd ? e3 : e2);   // P[g+8][ks*8+t4]
            uint32_t a2 = f2tf(odd ? f1 : f0);   // P[g][ks*8+t4+4]
            uint32_t a3 = f2tf(odd ? f3 : f2);   // P[g+8][ks*8+t4+4]
#pragma unroll
            for (int nt = 0; nt < 4; nt++) {
                uint32_t b0 = Vs[(ks * 8 + t4) * 40 + nt * 8 + g];
                uint32_t b1 = Vs[(ks * 8 + t4 + 4) * 40 + nt * 8 + g];
                mma_tf32(o[nt], a0, a1, a2, a3, b0, b1);
            }
        }
    }

    // ---- epilogue: normalize, write g_AO ----
    const float inv0 = 1.f / l0;
    const float inv1 = 1.f / l1;
    const int b = bh >> 3, h = bh & 7;
    const int r0 = q0 + wr + g;
    const int r1 = r0 + 8;
#pragma unroll
    for (int nt = 0; nt < 4; nt++) {
        int col = h * 32 + nt * 8 + 2 * t4;
        if (r0 < S_TOT) {
            float2 v = make_float2(o[nt][0] * inv0, o[nt][1] * inv0);
            *(float2*)&g_AO[((size_t)(b * S_TOT + r0)) * CDIM + col] = v;
        }
        if (r1 < S_TOT) {
            float2 v = make_float2(o[nt][2] * inv1, o[nt][3] * inv1);
            *(float2*)&g_AO[((size_t)(b * S_TOT + r1)) * CDIM + col] = v;
        }
    }
}

// ---------------------------------------------------------------------------
// LePE depthwise 5x5 conv
// ---------------------------------------------------------------------------
__global__ void lepe_kernel(const float* __restrict__ x,
                            const float* __restrict__ lw,
                            const float* __restrict__ lb) {
    const int c = threadIdx.x;
    const int p0 = blockIdx.x * 16;
    float w[25];
#pragma unroll
    for (int j = 0; j < 25; j++) w[j] = lw[c * 25 + j];
    const float bias = lb[c];
#pragma unroll 1
    for (int p = 0; p < 16; p++) {
        int pos = p0 + p;
        int b = pos / NPIX;
        int n = pos % NPIX;
        int y = n / 56, xx = n % 56;
        float acc = bias;
#pragma unroll
        for (int ky = -2; ky <= 2; ky++) {
            int yy = y + ky;
            if (yy < 0 || yy >= 56) continue;
#pragma unroll
            for (int kx = -2; kx <= 2; kx++) {
                int xc = xx + kx;
                if (xc < 0 || xc >= 56) continue;
                acc += x[((size_t)((b * 56 + yy) * 56 + xc)) * CDIM + c] *
                       w[(ky + 2) * 5 + (kx + 2)];
            }
        }
        g_AO[((size_t)(b * S_TOT + 1 + n)) * CDIM + c] += acc;
    }
}

// ---------------------------------------------------------------------------
// Projection GEMM with bias, routes rows to x_out / cls_out regions of d_out
// ---------------------------------------------------------------------------
__global__ void proj_gemm(const float* __restrict__ w,
                          const float* __restrict__ bias,
                          float* __restrict__ out) {
    __shared__ float Xt[32][68];
    __shared__ float Wt[32][68];
    const int tid = threadIdx.x;
    const int ty = tid >> 3, tx = tid & 7;
    const int m0 = blockIdx.x * 64, n0 = blockIdx.y * 64;
    const int M = BATCH * S_TOT;

    float acc[4][8];
#pragma unroll
    for (int i = 0; i < 4; i++)
#pragma unroll
        for (int j = 0; j < 8; j++) acc[i][j] = 0.f;

    for (int kc = 0; kc < 256; kc += 32) {
#pragma unroll
        for (int t = 0; t < 4; t++) {
            int g = tid + t * 128;
            int r = g >> 3, c4 = g & 7;
            int m = m0 + r;
            float4 v = make_float4(0.f, 0.f, 0.f, 0.f);
            if (m < M) v = *(const float4*)(g_AO + (size_t)m * CDIM + kc + c4 * 4);
            Xt[c4 * 4 + 0][r] = v.x; Xt[c4 * 4 + 1][r] = v.y;
            Xt[c4 * 4 + 2][r] = v.z; Xt[c4 * 4 + 3][r] = v.w;
            int n = n0 + r;
            float4 wv = *(const float4*)(w + (size_t)n * 256 + kc + c4 * 4);
            Wt[c4 * 4 + 0][r] = wv.x; Wt[c4 * 4 + 1][r] = wv.y;
            Wt[c4 * 4 + 2][r] = wv.z; Wt[c4 * 4 + 3][r] = wv.w;
        }
        __syncthreads();
#pragma unroll
        for (int kk = 0; kk < 32; kk++) {
            float4 xv  = *(float4*)&Xt[kk][ty * 4];
            float4 wv0 = *(float4*)&Wt[kk][tx * 8];
            float4 wv1 = *(float4*)&Wt[kk][tx * 8 + 4];
            float xr[4] = {xv.x, xv.y, xv.z, xv.w};
            float wr[8] = {wv0.x, wv0.y, wv0.z, wv0.w, wv1.x, wv1.y, wv1.z, wv1.w};
#pragma unroll
            for (int i = 0; i < 4; i++)
#pragma unroll
                for (int j = 0; j < 8; j++) acc[i][j] += xr[i] * wr[j];
        }
        __syncthreads();
    }

    const size_t cls_base = (size_t)BATCH * NPIX * CDIM;
#pragma unroll
    for (int i = 0; i < 4; i++) {
        int m = m0 + ty * 4 + i;
        if (m >= M) continue;
        int b = m / S_TOT, s = m % S_TOT;
#pragma unroll
        for (int jj = 0; jj < 2; jj++) {
            int n = n0 + tx * 8 + jj * 4;
            float4 bb = *(const float4*)(bias + n);
            float4 v = make_float4(acc[i][jj * 4] + bb.x, acc[i][jj * 4 + 1] + bb.y,
                                   acc[i][jj * 4 + 2] + bb.z, acc[i][jj * 4 + 3] + bb.w);
            float* dst;
            if (s == 0) dst = out + cls_base + (size_t)b * CDIM + n;
            else        dst = out + ((size_t)(b * NPIX + (s - 1))) * CDIM + n;
            *(float4*)dst = v;
        }
    }
}

// ---------------------------------------------------------------------------
extern "C" void kernel_launch(void* const* d_in, const int* in_sizes, int n_in,
                              void* d_out, int out_size) {
    (void)in_sizes; (void)n_in; (void)out_size;
    const float* x      = (const float*)d_in[0];
    const float* cls    = (const float*)d_in[1];
    const float* qkv_w  = (const float*)d_in[2];
    const float* proj_w = (const float*)d_in[3];
    const float* proj_b = (const float*)d_in[4];
    const float* lepe_w = (const float*)d_in[5];
    const float* lepe_b = (const float*)d_in[6];
    float* out = (float*)d_out;

    const int M = BATCH * S_TOT;
    dim3 qkvGrid((M + 63) / 64, 768 / 64);
    qkv_gemm<<<qkvGrid, 128>>>(x, cls, qkv_w);

    dim3 attGrid((S_TOT + 127) / 128, BATCH * NHEAD);  // 25 x 32
    attn_mma<<<attGrid, 256>>>();

    lepe_kernel<<<(BATCH * NPIX) / 16, 256>>>(x, lepe_w, lepe_b);

    dim3 projGrid((M + 63) / 64, 256 / 64);
    proj_gemm<<<projGrid, 128>>>(proj_w, proj_b, out);
}

// round 14
// speedup vs baseline: 2.9470x; 1.3705x over previous
#include <cuda_runtime.h>
#include <cstdint>

#define S_TOT 3137
#define NPIX  3136
#define NHEAD 8
#define HD    32
#define CDIM  256
#define BATCH 4
#define M_TOT (BATCH * S_TOT)
#define ATT_SCALE 0.17677669529663687f  // 32^-0.5

// ---------------------------------------------------------------------------
// scratch (allocation-free rule: device globals)
// ---------------------------------------------------------------------------
__device__ float g_Q[BATCH*NHEAD*S_TOT*HD];
__device__ float g_K[BATCH*NHEAD*S_TOT*HD];
__device__ float g_V[BATCH*NHEAD*S_TOT*HD];
__device__ float g_AO[BATCH*S_TOT*CDIM];

// ---------------------------------------------------------------------------
// mma.sync tf32 helpers (baseline sm_80 PTX — valid on compute_103)
// ---------------------------------------------------------------------------
__device__ __forceinline__ uint32_t f2tf(float f) {
    uint32_t u;
    asm("cvt.rna.tf32.f32 %0, %1;" : "=r"(u) : "f"(f));
    return u;
}
__device__ __forceinline__ void mma_tf32(float c[4],
                                         uint32_t a0, uint32_t a1, uint32_t a2, uint32_t a3,
                                         uint32_t b0, uint32_t b1) {
    asm volatile("mma.sync.aligned.m16n8k8.row.col.f32.tf32.tf32.f32 "
                 "{%0,%1,%2,%3}, {%4,%5,%6,%7}, {%8,%9}, {%0,%1,%2,%3};"
                 : "+f"(c[0]), "+f"(c[1]), "+f"(c[2]), "+f"(c[3])
                 : "r"(a0), "r"(a1), "r"(a2), "r"(a3), "r"(b0), "r"(b1));
}

// ===========================================================================
// Shared GEMM core: C[128 x 64] tile = X[128 x 256] @ W[64 x 256]^T (tf32).
// 256 threads / 8 warps; warp (wm = warp&3, wn = warp>>2) owns 32x32.
// Xs/Ws stride 36 words (conflict-free, same pattern as attention kernel).
// LoadX(dst16, m, kc, half): fill 16 tf32 words for X row m, cols
// [kc + half*16, kc + half*16 + 16).
// ===========================================================================
template <typename LoadX>
__device__ __forceinline__ void gemm_core(const float* __restrict__ wp,
                                          int m0, int n0,
                                          float acc[2][4][4],
                                          LoadX loadx) {
    __shared__ uint32_t Xs[128 * 36];
    __shared__ uint32_t Ws[64 * 36];
    const int tid  = threadIdx.x;
    const int lane = tid & 31;
    const int warp = tid >> 5;
    const int g  = lane >> 2;
    const int t4 = lane & 3;
    const int wm = warp & 3, wn = warp >> 2;

#pragma unroll
    for (int mt = 0; mt < 2; mt++)
#pragma unroll
        for (int nt = 0; nt < 4; nt++)
#pragma unroll
            for (int c = 0; c < 4; c++) acc[mt][nt][c] = 0.f;

    for (int kc = 0; kc < 256; kc += 32) {
        __syncthreads();
        {   // load X tile: 128 rows x 32 cols, 2 thr/row, 16 words each
            int row = tid >> 1, half = tid & 1;
            loadx(Xs + row * 36 + half * 16, m0 + row, kc, half);
        }
        {   // load W tile: 64 rows x 32 cols, 4 thr/row, 8 words each
            int nrow = tid >> 2, q4c = tid & 3;
            const float* wsrc = wp + (size_t)(n0 + nrow) * 256 + kc + q4c * 8;
            uint32_t* wdst = Ws + nrow * 36 + q4c * 8;
#pragma unroll
            for (int i = 0; i < 2; i++) {
                float4 v = *(const float4*)(wsrc + i * 4);
                wdst[i * 4 + 0] = f2tf(v.x); wdst[i * 4 + 1] = f2tf(v.y);
                wdst[i * 4 + 2] = f2tf(v.z); wdst[i * 4 + 3] = f2tf(v.w);
            }
        }
        __syncthreads();

#pragma unroll
        for (int ks = 0; ks < 4; ks++) {
            uint32_t a[2][4];
#pragma unroll
            for (int mt = 0; mt < 2; mt++) {
                int r = wm * 32 + mt * 16;
                int c = ks * 8 + t4;
                a[mt][0] = Xs[(r + g) * 36 + c];
                a[mt][1] = Xs[(r + g + 8) * 36 + c];
                a[mt][2] = Xs[(r + g) * 36 + c + 4];
                a[mt][3] = Xs[(r + g + 8) * 36 + c + 4];
            }
#pragma unroll
            for (int nt = 0; nt < 4; nt++) {
                uint32_t b0 = Ws[(wn * 32 + nt * 8 + g) * 36 + ks * 8 + t4];
                uint32_t b1 = Ws[(wn * 32 + nt * 8 + g) * 36 + ks * 8 + t4 + 4];
#pragma unroll
                for (int mt = 0; mt < 2; mt++)
                    mma_tf32(acc[mt][nt], a[mt][0], a[mt][1], a[mt][2],
                             a[mt][3], b0, b1);
            }
        }
    }
}

// ---------------------------------------------------------------------------
// QKV GEMM (tensor cores): [B*S,256] @ qkv_w^T -> scatter g_Q/g_K/g_V
// Grid: (ceil(M/128), 768/64)
// ---------------------------------------------------------------------------
__global__ void __launch_bounds__(256) qkv_mma(const float* __restrict__ x,
                                               const float* __restrict__ cls,
                                               const float* __restrict__ wp) {
    const int m0 = blockIdx.x * 128, n0 = blockIdx.y * 64;
    float acc[2][4][4];

    gemm_core(wp, m0, n0, acc,
        [&](uint32_t* dst, int m, int kc, int half) {
            bool ok = m < M_TOT;
            int b = ok ? m / S_TOT : 0, s = ok ? m % S_TOT : 0;
            const float* src = (s == 0) ? (cls + b * CDIM)
                                        : (x + (size_t)(b * NPIX + (s - 1)) * CDIM);
            src += kc + half * 16;
#pragma unroll
            for (int i = 0; i < 4; i++) {
                float4 v = ok ? *(const float4*)(src + i * 4)
                              : make_float4(0.f, 0.f, 0.f, 0.f);
                dst[i * 4 + 0] = f2tf(v.x); dst[i * 4 + 1] = f2tf(v.y);
                dst[i * 4 + 2] = f2tf(v.z); dst[i * 4 + 3] = f2tf(v.w);
            }
        });

    const int lane = threadIdx.x & 31;
    const int warp = threadIdx.x >> 5;
    const int g = lane >> 2, t4 = lane & 3;
    const int wm = warp & 3, wn = warp >> 2;

#pragma unroll
    for (int mt = 0; mt < 2; mt++) {
        int mr0 = m0 + wm * 32 + mt * 16 + g;
        int mr1 = mr0 + 8;
#pragma unroll
        for (int nt = 0; nt < 4; nt++) {
            int n = n0 + wn * 32 + nt * 8 + 2 * t4;
            int sec = n >> 8, h = (n >> 5) & 7, d = n & 31;
            float* base = (sec == 0) ? g_Q : ((sec == 1) ? g_K : g_V);
            if (mr0 < M_TOT) {
                int b = mr0 / S_TOT, s = mr0 % S_TOT;
                *(float2*)&base[(((size_t)(b * NHEAD + h) * S_TOT + s) * HD) + d] =
                    make_float2(acc[mt][nt][0], acc[mt][nt][1]);
            }
            if (mr1 < M_TOT) {
                int b = mr1 / S_TOT, s = mr1 % S_TOT;
                *(float2*)&base[(((size_t)(b * NHEAD + h) * S_TOT + s) * HD) + d] =
                    make_float2(acc[mt][nt][2], acc[mt][nt][3]);
            }
        }
    }
}

// ---------------------------------------------------------------------------
// Projection GEMM (tensor cores) with bias + cls/spatial routing.
// Grid: (ceil(M/128), 256/64)
// ---------------------------------------------------------------------------
__global__ void __launch_bounds__(256) proj_mma(const float* __restrict__ wp,
                                                const float* __restrict__ bias,
                                                float* __restrict__ out) {
    const int m0 = blockIdx.x * 128, n0 = blockIdx.y * 64;
    float acc[2][4][4];

    gemm_core(wp, m0, n0, acc,
        [&](uint32_t* dst, int m, int kc, int half) {
            bool ok = m < M_TOT;
            const float* src = g_AO + (size_t)(ok ? m : 0) * CDIM + kc + half * 16;
#pragma unroll
            for (int i = 0; i < 4; i++) {
                float4 v = ok ? *(const float4*)(src + i * 4)
                              : make_float4(0.f, 0.f, 0.f, 0.f);
                dst[i * 4 + 0] = f2tf(v.x); dst[i * 4 + 1] = f2tf(v.y);
                dst[i * 4 + 2] = f2tf(v.z); dst[i * 4 + 3] = f2tf(v.w);
            }
        });

    const int lane = threadIdx.x & 31;
    const int warp = threadIdx.x >> 5;
    const int g = lane >> 2, t4 = lane & 3;
    const int wm = warp & 3, wn = warp >> 2;
    const size_t cls_base = (size_t)BATCH * NPIX * CDIM;

#pragma unroll
    for (int mt = 0; mt < 2; mt++) {
        int mr0 = m0 + wm * 32 + mt * 16 + g;
        int mr1 = mr0 + 8;
#pragma unroll
        for (int nt = 0; nt < 4; nt++) {
            int n = n0 + wn * 32 + nt * 8 + 2 * t4;
            float2 bb = *(const float2*)(bias + n);
            if (mr0 < M_TOT) {
                int b = mr0 / S_TOT, s = mr0 % S_TOT;
                float* dstp = (s == 0) ? (out + cls_base + (size_t)b * CDIM + n)
                                       : (out + ((size_t)(b * NPIX + (s - 1))) * CDIM + n);
                *(float2*)dstp = make_float2(acc[mt][nt][0] + bb.x,
                                             acc[mt][nt][1] + bb.y);
            }
            if (mr1 < M_TOT) {
                int b = mr1 / S_TOT, s = mr1 % S_TOT;
                float* dstp = (s == 0) ? (out + cls_base + (size_t)b * CDIM + n)
                                       : (out + ((size_t)(b * NPIX + (s - 1))) * CDIM + n);
                *(float2*)dstp = make_float2(acc[mt][nt][2] + bb.x,
                                             acc[mt][nt][3] + bb.y);
            }
        }
    }
}

// ---------------------------------------------------------------------------
// Flash attention via mma.sync tf32 (unchanged from R10 — passing, 3e-4)
// ---------------------------------------------------------------------------
#define NKT_64 50

__global__ void __launch_bounds__(256) attn_mma() {
    __shared__ uint32_t Qs[128 * 36];
    __shared__ uint32_t Ks[64 * 36];
    __shared__ uint32_t Vs[64 * 40];

    const int tid  = threadIdx.x;
    const int lane = tid & 31;
    const int warp = tid >> 5;
    const int g  = lane >> 2;
    const int t4 = lane & 3;
    const int L0 = (lane & ~3) + (t4 >> 1);
    const int L1 = L0 + 2;
    const bool odd = t4 & 1;
    const int q0 = blockIdx.x * 128;
    const int bh = blockIdx.y;

    const float* Qg = g_Q + (size_t)bh * S_TOT * HD;
    const float* Kg = g_K + (size_t)bh * S_TOT * HD;
    const float* Vg = g_V + (size_t)bh * S_TOT * HD;

    {
        int row = tid >> 1, half = tid & 1;
        int qg = q0 + row;
        bool ok = qg < S_TOT;
        const float* src = Qg + (size_t)(ok ? qg : 0) * HD + half * 16;
        uint32_t* dst = Qs + row * 36 + half * 16;
#pragma unroll
        for (int i = 0; i < 4; i++) {
            float4 v = ok ? *(const float4*)(src + i * 4) : make_float4(0.f,0.f,0.f,0.f);
            dst[i * 4 + 0] = f2tf(v.x);
            dst[i * 4 + 1] = f2tf(v.y);
            dst[i * 4 + 2] = f2tf(v.z);
            dst[i * 4 + 3] = f2tf(v.w);
        }
    }
    __syncthreads();

    const int wr = warp * 16;
    uint32_t qa[4][4];
#pragma unroll
    for (int ks = 0; ks < 4; ks++) {
        int c = ks * 8 + t4;
        qa[ks][0] = Qs[(wr + g) * 36 + c];
        qa[ks][1] = Qs[(wr + g + 8) * 36 + c];
        qa[ks][2] = Qs[(wr + g) * 36 + c + 4];
        qa[ks][3] = Qs[(wr + g + 8) * 36 + c + 4];
    }

    float o[4][4];
#pragma unroll
    for (int nt = 0; nt < 4; nt++)
#pragma unroll
        for (int c = 0; c < 4; c++) o[nt][c] = 0.f;
    float l0 = 0.f, l1 = 0.f;

    for (int kt = 0; kt < NKT_64; kt++) {
        __syncthreads();

        {
            int row = tid >> 2, q4 = tid & 3;
            int kr = kt * 64 + row;
            bool ok = kr < S_TOT;
            const float* ks_ = Kg + (size_t)(ok ? kr : 0) * HD + q4 * 8;
            const float* vs_ = Vg + (size_t)(ok ? kr : 0) * HD + q4 * 8;
            uint32_t* kd = Ks + row * 36 + q4 * 8;
            uint32_t* vd = Vs + row * 40 + q4 * 8;
#pragma unroll
            for (int i = 0; i < 2; i++) {
                float4 kv = ok ? *(const float4*)(ks_ + i * 4) : make_float4(0.f,0.f,0.f,0.f);
                float4 vv = ok ? *(const float4*)(vs_ + i * 4) : make_float4(0.f,0.f,0.f,0.f);
                kd[i * 4 + 0] = f2tf(kv.x); kd[i * 4 + 1] = f2tf(kv.y);
                kd[i * 4 + 2] = f2tf(kv.z); kd[i * 4 + 3] = f2tf(kv.w);
                vd[i * 4 + 0] = f2tf(vv.x); vd[i * 4 + 1] = f2tf(vv.y);
                vd[i * 4 + 2] = f2tf(vv.z); vd[i * 4 + 3] = f2tf(vv.w);
            }
        }
        __syncthreads();

        float s[8][4];
#pragma unroll
        for (int nt = 0; nt < 8; nt++)
#pragma unroll
            for (int c = 0; c < 4; c++) s[nt][c] = 0.f;
#pragma unroll
        for (int ks = 0; ks < 4; ks++) {
#pragma unroll
            for (int nt = 0; nt < 8; nt++) {
                uint32_t b0 = Ks[(nt * 8 + g) * 36 + ks * 8 + t4];
                uint32_t b1 = Ks[(nt * 8 + g) * 36 + ks * 8 + t4 + 4];
                mma_tf32(s[nt], qa[ks][0], qa[ks][1], qa[ks][2], qa[ks][3], b0, b1);
            }
        }

        float l0a = 0.f, l1a = 0.f;
#pragma unroll
        for (int nt = 0; nt < 8; nt++) {
            int kb = kt * 64 + nt * 8 + 2 * t4;
            float p0 = (kb     < S_TOT) ? __expf(s[nt][0] * ATT_SCALE) : 0.f;
            float p1 = (kb + 1 < S_TOT) ? __expf(s[nt][1] * ATT_SCALE) : 0.f;
            float p2 = (kb     < S_TOT) ? __expf(s[nt][2] * ATT_SCALE) : 0.f;
            float p3 = (kb + 1 < S_TOT) ? __expf(s[nt][3] * ATT_SCALE) : 0.f;
            l0a += p0 + p1;
            l1a += p2 + p3;
            s[nt][0] = p0; s[nt][1] = p1; s[nt][2] = p2; s[nt][3] = p3;
        }
        l0a += __shfl_xor_sync(0xffffffffu, l0a, 1);
        l0a += __shfl_xor_sync(0xffffffffu, l0a, 2);
        l1a += __shfl_xor_sync(0xffffffffu, l1a, 1);
        l1a += __shfl_xor_sync(0xffffffffu, l1a, 2);
        l0 += l0a; l1 += l1a;

#pragma unroll
        for (int ks = 0; ks < 8; ks++) {
            float e0 = __shfl_sync(0xffffffffu, s[ks][0], L0);
            float e1 = __shfl_sync(0xffffffffu, s[ks][1], L0);
            float e2 = __shfl_sync(0xffffffffu, s[ks][2], L0);
            float e3 = __shfl_sync(0xffffffffu, s[ks][3], L0);
            float f0 = __shfl_sync(0xffffffffu, s[ks][0], L1);
            float f1 = __shfl_sync(0xffffffffu, s[ks][1], L1);
            float f2 = __shfl_sync(0xffffffffu, s[ks][2], L1);
            float f3 = __shfl_sync(0xffffffffu, s[ks][3], L1);
            uint32_t a0 = f2tf(odd ? e1 : e0);
            uint32_t a1 = f2tf(odd ? e3 : e2);
            uint32_t a2 = f2tf(odd ? f1 : f0);
            uint32_t a3 = f2tf(odd ? f3 : f2);
#pragma unroll
            for (int nt = 0; nt < 4; nt++) {
                uint32_t b0 = Vs[(ks * 8 + t4) * 40 + nt * 8 + g];
                uint32_t b1 = Vs[(ks * 8 + t4 + 4) * 40 + nt * 8 + g];
                mma_tf32(o[nt], a0, a1, a2, a3, b0, b1);
            }
        }
    }

    const float inv0 = 1.f / l0;
    const float inv1 = 1.f / l1;
    const int b = bh >> 3, h = bh & 7;
    const int r0 = q0 + wr + g;
    const int r1 = r0 + 8;
#pragma unroll
    for (int nt = 0; nt < 4; nt++) {
        int col = h * 32 + nt * 8 + 2 * t4;
        if (r0 < S_TOT) {
            float2 v = make_float2(o[nt][0] * inv0, o[nt][1] * inv0);
            *(float2*)&g_AO[((size_t)(b * S_TOT + r0)) * CDIM + col] = v;
        }
        if (r1 < S_TOT) {
            float2 v = make_float2(o[nt][2] * inv1, o[nt][3] * inv1);
            *(float2*)&g_AO[((size_t)(b * S_TOT + r1)) * CDIM + col] = v;
        }
    }
}

// ---------------------------------------------------------------------------
// LePE depthwise 5x5 conv (unchanged)
// ---------------------------------------------------------------------------
__global__ void lepe_kernel(const float* __restrict__ x,
                            const float* __restrict__ lw,
                            const float* __restrict__ lb) {
    const int c = threadIdx.x;
    const int p0 = blockIdx.x * 16;
    float w[25];
#pragma unroll
    for (int j = 0; j < 25; j++) w[j] = lw[c * 25 + j];
    const float bias = lb[c];
#pragma unroll 1
    for (int p = 0; p < 16; p++) {
        int pos = p0 + p;
        int b = pos / NPIX;
        int n = pos % NPIX;
        int y = n / 56, xx = n % 56;
        float acc = bias;
#pragma unroll
        for (int ky = -2; ky <= 2; ky++) {
            int yy = y + ky;
            if (yy < 0 || yy >= 56) continue;
#pragma unroll
            for (int kx = -2; kx <= 2; kx++) {
                int xc = xx + kx;
                if (xc < 0 || xc >= 56) continue;
                acc += x[((size_t)((b * 56 + yy) * 56 + xc)) * CDIM + c] *
                       w[(ky + 2) * 5 + (kx + 2)];
            }
        }
        g_AO[((size_t)(b * S_TOT + 1 + n)) * CDIM + c] += acc;
    }
}

// ---------------------------------------------------------------------------
extern "C" void kernel_launch(void* const* d_in, const int* in_sizes, int n_in,
                              void* d_out, int out_size) {
    (void)in_sizes; (void)n_in; (void)out_size;
    const float* x      = (const float*)d_in[0];
    const float* cls    = (const float*)d_in[1];
    const float* qkv_w  = (const float*)d_in[2];
    const float* proj_w = (const float*)d_in[3];
    const float* proj_b = (const float*)d_in[4];
    const float* lepe_w = (const float*)d_in[5];
    const float* lepe_b = (const float*)d_in[6];
    float* out = (float*)d_out;

    dim3 qkvGrid((M_TOT + 127) / 128, 768 / 64);   // 99 x 12
    qkv_mma<<<qkvGrid, 256>>>(x, cls, qkv_w);

    dim3 attGrid((S_TOT + 127) / 128, BATCH * NHEAD);  // 25 x 32
    attn_mma<<<attGrid, 256>>>();

    lepe_kernel<<<(BATCH * NPIX) / 16, 256>>>(x, lepe_w, lepe_b);

    dim3 projGrid((M_TOT + 127) / 128, 256 / 64);  // 99 x 4
    proj_mma<<<projGrid, 256>>>(proj_w, proj_b, out);
}